// round 10
// baseline (speedup 1.0000x reference)
#include <cuda_runtime.h>
#include <cuda_fp16.h>
#include <math.h>
#include <float.h>
#include <cstdint>

// Problem constants
#define BB 2
#define SS 2048
#define HH 4096
#define NHEAD 32
#define NKVH 2
#define HDIM 128
#define ROT 64
#define QKV_N ((NHEAD + 2*NKVH) * HDIM)   // 4608
#define TOKENS (BB*SS)                     // 4096

// Scratch (device globals; allocation-free) — all fp16
__device__ __half g_hs [(size_t)TOKENS * HH];            // fp16 hidden_states
__device__ __half g_qkv[(size_t)TOKENS * QKV_N];
__device__ __half g_attn[(size_t)TOKENS * HH];
__device__ __half g_wt [(size_t)QKV_N * HH];
__device__ __half g_vt [(size_t)BB * NKVH * HDIM * SS];  // V^T: [b][kvh][d][t]

// mma.sync m16n8k16 fp16 -> fp32 accum
__device__ __forceinline__ void mma_f16(float* c, const uint32_t* a, const uint32_t* b) {
    asm volatile("mma.sync.aligned.m16n8k16.row.col.f32.f16.f16.f32 "
        "{%0,%1,%2,%3}, {%4,%5,%6,%7}, {%8,%9}, {%0,%1,%2,%3};"
        : "+f"(c[0]), "+f"(c[1]), "+f"(c[2]), "+f"(c[3])
        : "r"(a[0]), "r"(a[1]), "r"(a[2]), "r"(a[3]), "r"(b[0]), "r"(b[1]));
}

__device__ __forceinline__ uint32_t pack_h2(float x, float y) {
    __half2 h = __floats2half2_rn(x, y);
    return *(uint32_t*)&h;
}

__device__ __forceinline__ uint32_t smem_u32(const void* p) {
    uint32_t a;
    asm("{ .reg .u64 t; cvta.to.shared.u64 t, %1; cvt.u32.u64 %0, t; }" : "=r"(a) : "l"(p));
    return a;
}

#define CP16(dst, src) \
    asm volatile("cp.async.cg.shared.global [%0], [%1], 16;" :: "r"(dst), "l"(src) : "memory")
#define CP_COMMIT() asm volatile("cp.async.commit_group;" ::: "memory")
#define CP_WAIT1()  asm volatile("cp.async.wait_group 1;" ::: "memory")
#define CP_WAIT0()  asm volatile("cp.async.wait_group 0;" ::: "memory")

#define LDSM4(r0, r1, r2, r3, addr) \
    asm volatile("ldmatrix.sync.aligned.m8n8.x4.shared.b16 {%0,%1,%2,%3}, [%4];" \
        : "=r"(r0), "=r"(r1), "=r"(r2), "=r"(r3) : "r"(addr))

// ---------------------------------------------------------------------------
// fp32 -> fp16 bulk convert (hidden_states)
// ---------------------------------------------------------------------------
__global__ __launch_bounds__(256)
void f2h_kernel(const float* __restrict__ in, __half* __restrict__ out)
{
    size_t i = ((size_t)blockIdx.x * 256 + threadIdx.x) * 8;
    float4 a = *(const float4*)(in + i);
    float4 b = *(const float4*)(in + i + 4);
    uint4 o;
    o.x = pack_h2(a.x, a.y); o.y = pack_h2(a.z, a.w);
    o.z = pack_h2(b.x, b.y); o.w = pack_h2(b.z, b.w);
    *(uint4*)(out + i) = o;
}

// ---------------------------------------------------------------------------
// Weight transpose + fp16 convert: W[K,N] fp32 row-major -> Wt[N,K] fp16
// ---------------------------------------------------------------------------
__global__ __launch_bounds__(256)
void transpose_f16_kernel(const float* __restrict__ W, __half* __restrict__ Wt, int K, int N)
{
    __shared__ float t[32][33];
    const int n0 = blockIdx.x * 32;
    const int k0 = blockIdx.y * 32;
    const int x = threadIdx.x, y = threadIdx.y;
    #pragma unroll
    for (int j = 0; j < 32; j += 8)
        t[y + j][x] = W[(size_t)(k0 + y + j) * N + n0 + x];
    __syncthreads();
    const int tid = y * 32 + x;
    #pragma unroll
    for (int p = 0; p < 2; ++p) {
        int task = p * 256 + tid;
        int r = task >> 4;
        int c = task & 15;
        __half2 h = __floats2half2_rn(t[2 * c][r], t[2 * c + 1][r]);
        *(__half2*)&Wt[(size_t)(n0 + r) * K + k0 + 2 * c] = h;
    }
}

// ---------------------------------------------------------------------------
// V transpose: g_qkv V region [token][d] -> g_vt [b][kvh][d][token]
// ---------------------------------------------------------------------------
__global__ __launch_bounds__(256)
void vtrans_kernel(const __half* __restrict__ qkv, __half* __restrict__ vt)
{
    __shared__ __half t[32][34];
    const int bk = blockIdx.z;
    const int d0 = blockIdx.y * 32;
    const int t0 = blockIdx.x * 32;
    const int b = bk >> 1, kvh = bk & 1;
    const int x = threadIdx.x, y = threadIdx.y;
    const __half* src = qkv + (size_t)(b * SS + t0) * QKV_N
                        + (NHEAD + NKVH) * HDIM + kvh * HDIM + d0;
    #pragma unroll
    for (int j = 0; j < 32; j += 8)
        t[y + j][x] = src[(size_t)(y + j) * QKV_N + x];
    __syncthreads();
    __half* dst = vt + ((size_t)bk * HDIM + d0) * SS + t0;
    #pragma unroll
    for (int j = 0; j < 32; j += 8)
        dst[(size_t)(y + j) * SS + x] = t[x][y + j];
}

// ---------------------------------------------------------------------------
// fp16 GEMM v2: C[M,N] = A[M,K] @ Bt[N,K]^T (+bias)
// BM=128, BN=256, BK=32, 256 thr, 8 warps (2x4), warp tile 64x64.
// Row-major smem tiles, row stride 80B (32 halves + 8 pad).
// 3-stage cp.async pipeline; fragments via ldmatrix.x4.
// QKV mode: C half + bias. Dense: C float, no bias.
// ---------------------------------------------------------------------------
#define G2_RS 80
#define G2_ABUF 10240                 // 128 rows x 80B
#define G2_BBUF 20480                 // 256 rows x 80B
#define G2_STAGE (G2_ABUF + G2_BBUF)  // 30720
#define G2_SMEM (3 * G2_STAGE)        // 92160

template<bool QKV>
__global__ __launch_bounds__(256, 1)
void mma_gemm_v2(const __half* __restrict__ A, const __half* __restrict__ Bt,
                 const float* __restrict__ bias, void* __restrict__ Cv,
                 int M, int N, int K)
{
    extern __shared__ char g2sm[];
    const uint32_t sb = smem_u32(g2sm);

    const int tid  = threadIdx.x;
    const int wid  = tid >> 5;
    const int lane = tid & 31;
    const int lg   = lane >> 2;
    const int lt   = lane & 3;
    const int m_warp = (wid & 1) * 64;
    const int n_warp = (wid >> 1) * 64;
    const int rowBase = blockIdx.y * 128;
    const int colBase = blockIdx.x * 256;

    // ldmatrix lane offsets (within a 16-row x 32-half block, stride 80B)
    const uint32_t a_loff = ((((lane >> 3) & 1) * 8 + (lane & 7)) * G2_RS) + (lane >> 4) * 16;
    const uint32_t b_loff = (((lane & 7) + ((lane >> 4) & 1) * 8) * G2_RS) + ((lane >> 3) & 1) * 16;

    // fill task indices
    const int ar = tid >> 2;           // A rows handled: ar, ar+64
    const int ac = (tid & 3) * 16;     // byte offset in row (c*16)
    const int ah = (tid & 3) * 8;      // half offset in row

    float acc[4][8][4];
    #pragma unroll
    for (int i = 0; i < 4; ++i)
        #pragma unroll
        for (int j = 0; j < 8; ++j)
            #pragma unroll
            for (int r = 0; r < 4; ++r) acc[i][j][r] = 0.f;

    auto fill = [&](int kt, int s) {
        uint32_t Ad = sb + s * G2_STAGE;
        uint32_t Bd = Ad + G2_ABUF;
        const __half* As = A + (size_t)rowBase * K + kt;
        const __half* Bs = Bt + (size_t)colBase * K + kt;
        #pragma unroll
        for (int p = 0; p < 2; ++p) {
            int r = ar + p * 64;
            CP16(Ad + (uint32_t)r * G2_RS + ac, As + (size_t)r * K + ah);
        }
        #pragma unroll
        for (int p = 0; p < 4; ++p) {
            int r = ar + p * 64;
            CP16(Bd + (uint32_t)r * G2_RS + ac, Bs + (size_t)r * K + ah);
        }
    };

    auto compute = [&](int s) {
        const uint32_t Ab = sb + s * G2_STAGE + (uint32_t)m_warp * G2_RS + a_loff;
        const uint32_t Bb = sb + s * G2_STAGE + G2_ABUF + (uint32_t)n_warp * G2_RS + b_loff;
        #pragma unroll
        for (int ks = 0; ks < 2; ++ks) {
            uint32_t afr[4][4], bfr[8][2];
            #pragma unroll
            for (int i = 0; i < 4; ++i)
                LDSM4(afr[i][0], afr[i][1], afr[i][2], afr[i][3],
                      Ab + (uint32_t)(i * 16) * G2_RS + ks * 32);
            #pragma unroll
            for (int jp = 0; jp < 4; ++jp) {
                uint32_t r0, r1, r2, r3;
                LDSM4(r0, r1, r2, r3, Bb + (uint32_t)(jp * 16) * G2_RS + ks * 32);
                bfr[2 * jp][0] = r0; bfr[2 * jp][1] = r1;
                bfr[2 * jp + 1][0] = r2; bfr[2 * jp + 1][1] = r3;
            }
            #pragma unroll
            for (int i = 0; i < 4; ++i)
                #pragma unroll
                for (int j = 0; j < 8; ++j)
                    mma_f16(acc[i][j], afr[i], bfr[j]);
        }
    };

    const int NIT = K / 32;
    fill(0, 0);  CP_COMMIT();
    fill(32, 1); CP_COMMIT();

    int s = 0;
    for (int t = 0; t < NIT; ++t) {
        if (t + 1 < NIT) { CP_WAIT1(); } else { CP_WAIT0(); }
        __syncthreads();
        if (t + 2 < NIT) {
            int s2 = s + 2; if (s2 >= 3) s2 -= 3;
            fill((t + 2) * 32, s2);
            CP_COMMIT();
        }
        compute(s);
        if (++s == 3) s = 0;
    }

    #pragma unroll
    for (int i = 0; i < 4; ++i) {
        #pragma unroll
        for (int j = 0; j < 8; ++j) {
            int row = rowBase + m_warp + i * 16 + lg;
            int col = colBase + n_warp + j * 8 + lt * 2;
            if (QKV) {
                __half* C = (__half*)Cv;
                float b0 = bias[col], b1 = bias[col + 1];
                *(__half2*)&C[(size_t)row * N + col] =
                    __floats2half2_rn(acc[i][j][0] + b0, acc[i][j][1] + b1);
                *(__half2*)&C[(size_t)(row + 8) * N + col] =
                    __floats2half2_rn(acc[i][j][2] + b0, acc[i][j][3] + b1);
            } else {
                float* C = (float*)Cv;
                float2 v0 = { acc[i][j][0], acc[i][j][1] };
                float2 v1 = { acc[i][j][2], acc[i][j][3] };
                *(float2*)&C[(size_t)row * N + col]       = v0;
                *(float2*)&C[(size_t)(row + 8) * N + col] = v1;
            }
        }
    }
}

// ---------------------------------------------------------------------------
// GLM RoPE, in-place on fp16 qkv (rotation math in fp32)
// ---------------------------------------------------------------------------
__global__ void rope_kernel(__half* __restrict__ qkv, const int* __restrict__ positions)
{
    int idx = blockIdx.x * blockDim.x + threadIdx.x;
    const int total = TOKENS * (NHEAD + NKVH) * (ROT / 2);
    if (idx >= total) return;
    int i    = idx & 31;
    int head = (idx >> 5) % (NHEAD + NKVH);
    int tok  = idx / ((NHEAD + NKVH) * 32);

    float pos = (float)positions[tok];
    float inv = __powf(10000.0f, -(float)i * (1.0f / 32.0f));
    float ang = pos * inv;
    float c, s;
    sincosf(ang, &s, &c);
    int col = (head < NHEAD) ? head * HDIM : (NHEAD * HDIM + (head - NHEAD) * HDIM);
    __half2* p = (__half2*)(qkv + (size_t)tok * QKV_N + col + 2 * i);
    float2 x = __half22float2(*p);
    *p = __floats2half2_rn(x.x * c - x.y * s, x.x * s + x.y * c);
}

// ---------------------------------------------------------------------------
// Flash attention (unchanged from round 9 — cp.async + ldmatrix)
// ---------------------------------------------------------------------------
#define FL_K_BYTES 17408
#define FL_V_BYTES 18432
#define FL_SMEM_BYTES (2*FL_K_BYTES + 2*FL_V_BYTES)   // 71680

__global__ __launch_bounds__(128, 3)
void flash_mma_kernel(const __half* __restrict__ qkv, const __half* __restrict__ vt,
                      __half* __restrict__ attn_out)
{
    extern __shared__ uint4 smu[];
    const uint32_t sb = smem_u32(smu);

    const int qt = blockIdx.x;
    const int bh = blockIdx.y;
    const int b  = bh >> 5;
    const int h  = bh & 31;
    const int kvh = h >> 4;
    const int tid = threadIdx.x;
    const int wid = tid >> 5;
    const int lane = tid & 31;
    const int lg = lane >> 2, lt = lane & 3;
    const int gq = lane >> 3, rq = lane & 7;
    const float scale = 0.08838834764831845f;

    const uint4* qg4 = (const uint4*)(qkv + (size_t)(b * SS + qt * 64) * QKV_N + h * HDIM);
    #pragma unroll
    for (int p = 0; p < 8; ++p) {
        int idx = p * 128 + tid;
        smu[(idx >> 4) * 17 + (idx & 15)] = qg4[(size_t)(idx >> 4) * 576 + (idx & 15)];
    }
    __syncthreads();
    uint32_t qa[8][4];
    {
        const uint32_t* Qw = (const uint32_t*)smu;
        int q0 = (wid * 16 + lg) * 68 + lt;
        int q1 = q0 + 8 * 68;
        #pragma unroll
        for (int kc = 0; kc < 8; ++kc) {
            qa[kc][0] = Qw[q0 + kc * 8];
            qa[kc][1] = Qw[q1 + kc * 8];
            qa[kc][2] = Qw[q0 + kc * 8 + 4];
            qa[kc][3] = Qw[q1 + kc * 8 + 4];
        }
    }
    __syncthreads();

    float oacc[16][4];
    #pragma unroll
    for (int j = 0; j < 16; ++j)
        #pragma unroll
        for (int r = 0; r < 4; ++r) oacc[j][r] = 0.f;
    float m0 = -3.0e38f, m1 = -3.0e38f, l0 = 0.f, l1 = 0.f;

    const __half* kbase = qkv + (size_t)b * SS * QKV_N + NHEAD * HDIM + kvh * HDIM;
    const __half* vbase = vt + (size_t)(b * NKVH + kvh) * HDIM * SS;

    auto fill = [&](int kt, int buf) {
        uint32_t Kd = sb + buf * FL_K_BYTES;
        uint32_t Vd = sb + 2 * FL_K_BYTES + buf * FL_V_BYTES;
        const uint4* ks = (const uint4*)(kbase + (size_t)(kt * 64) * QKV_N);
        #pragma unroll
        for (int p = 0; p < 8; ++p) {
            int idx = p * 128 + tid;
            int n = idx >> 4, c = idx & 15;
            CP16(Kd + (uint32_t)(n * 17 + c) * 16, ks + (size_t)n * 576 + c);
        }
        const uint4* vs = (const uint4*)(vbase + kt * 64);
        #pragma unroll
        for (int p = 0; p < 8; ++p) {
            int idx = p * 128 + tid;
            int f = idx >> 3, c = idx & 7;
            CP16(Vd + (uint32_t)(f * 9 + c) * 16, vs + (size_t)f * 256 + c);
        }
    };

    fill(0, 0);
    CP_COMMIT();

    const int row0g = qt * 64 + wid * 16 + lg;
    const int row1g = row0g + 8;

    for (int kt = 0; kt <= qt; ++kt) {
        if (kt < qt) { fill(kt + 1, (kt + 1) & 1); CP_COMMIT(); CP_WAIT1(); }
        else         { CP_WAIT0(); }
        __syncthreads();

        const uint32_t Kb = sb + (kt & 1) * FL_K_BYTES
                            + rq * 272 + (gq >> 1) * 32 + (gq & 1) * 16;
        const uint32_t Vb = sb + 2 * FL_K_BYTES + (kt & 1) * FL_V_BYTES
                            + rq * 144 + (gq >> 1) * 32 + (gq & 1) * 16;

        float sacc[8][4];
        #pragma unroll
        for (int j = 0; j < 8; ++j)
            #pragma unroll
            for (int r = 0; r < 4; ++r) sacc[j][r] = 0.f;

        #pragma unroll
        for (int kp2 = 0; kp2 < 4; ++kp2) {
            #pragma unroll
            for (int j = 0; j < 8; ++j) {
                uint32_t b0, b1, b2, b3;
                LDSM4(b0, b1, b2, b3, Kb + j * 2176 + kp2 * 64);
                uint32_t be[2] = { b0, b1 }, bo[2] = { b2, b3 };
                mma_f16(sacc[j], qa[2 * kp2],     be);
                mma_f16(sacc[j], qa[2 * kp2 + 1], bo);
            }
        }

        #pragma unroll
        for (int j = 0; j < 8; ++j)
            #pragma unroll
            for (int r = 0; r < 4; ++r) sacc[j][r] *= scale;
        if (kt == qt) {
            #pragma unroll
            for (int j = 0; j < 8; ++j) {
                int col = kt * 64 + j * 8 + 2 * lt;
                if (col     > row0g) sacc[j][0] = -3.0e38f;
                if (col + 1 > row0g) sacc[j][1] = -3.0e38f;
                if (col     > row1g) sacc[j][2] = -3.0e38f;
                if (col + 1 > row1g) sacc[j][3] = -3.0e38f;
            }
        }

        float mx0 = -3.0e38f, mx1 = -3.0e38f;
        #pragma unroll
        for (int j = 0; j < 8; ++j) {
            mx0 = fmaxf(mx0, fmaxf(sacc[j][0], sacc[j][1]));
            mx1 = fmaxf(mx1, fmaxf(sacc[j][2], sacc[j][3]));
        }
        mx0 = fmaxf(mx0, __shfl_xor_sync(0xffffffffu, mx0, 1));
        mx0 = fmaxf(mx0, __shfl_xor_sync(0xffffffffu, mx0, 2));
        mx1 = fmaxf(mx1, __shfl_xor_sync(0xffffffffu, mx1, 1));
        mx1 = fmaxf(mx1, __shfl_xor_sync(0xffffffffu, mx1, 2));
        float nm0 = fmaxf(m0, mx0), nm1 = fmaxf(m1, mx1);
        float a0 = __expf(m0 - nm0), a1 = __expf(m1 - nm1);
        m0 = nm0; m1 = nm1;
        float rs0 = 0.f, rs1 = 0.f;
        #pragma unroll
        for (int j = 0; j < 8; ++j) {
            sacc[j][0] = __expf(sacc[j][0] - nm0);
            sacc[j][1] = __expf(sacc[j][1] - nm0);
            sacc[j][2] = __expf(sacc[j][2] - nm1);
            sacc[j][3] = __expf(sacc[j][3] - nm1);
            rs0 += sacc[j][0] + sacc[j][1];
            rs1 += sacc[j][2] + sacc[j][3];
        }
        rs0 += __shfl_xor_sync(0xffffffffu, rs0, 1);
        rs0 += __shfl_xor_sync(0xffffffffu, rs0, 2);
        rs1 += __shfl_xor_sync(0xffffffffu, rs1, 1);
        rs1 += __shfl_xor_sync(0xffffffffu, rs1, 2);
        l0 = l0 * a0 + rs0;
        l1 = l1 * a1 + rs1;

        #pragma unroll
        for (int j = 0; j < 16; ++j) {
            oacc[j][0] *= a0; oacc[j][1] *= a0;
            oacc[j][2] *= a1; oacc[j][3] *= a1;
        }

        uint32_t pa[4][4];
        #pragma unroll
        for (int kp = 0; kp < 4; ++kp) {
            pa[kp][0] = pack_h2(sacc[2 * kp][0],     sacc[2 * kp][1]);
            pa[kp][1] = pack_h2(sacc[2 * kp][2],     sacc[2 * kp][3]);
            pa[kp][2] = pack_h2(sacc[2 * kp + 1][0], sacc[2 * kp + 1][1]);
            pa[kp][3] = pack_h2(sacc[2 * kp + 1][2], sacc[2 * kp + 1][3]);
        }

        #pragma unroll
        for (int kp2 = 0; kp2 < 2; ++kp2) {
            #pragma unroll
            for (int jf = 0; jf < 16; ++jf) {
                uint32_t r0, r1, r2, r3;
                LDSM4(r0, r1, r2, r3, Vb + jf * 1152 + kp2 * 64);
                uint32_t ve[2] = { r0, r1 }, vo[2] = { r2, r3 };
                mma_f16(oacc[jf], pa[2 * kp2],     ve);
                mma_f16(oacc[jf], pa[2 * kp2 + 1], vo);
            }
        }
        __syncthreads();
    }

    float il0 = 1.0f / l0, il1 = 1.0f / l1;
    __half* ob = attn_out + (size_t)(b * SS + qt * 64 + wid * 16) * HH + h * HDIM;
    #pragma unroll
    for (int j = 0; j < 16; ++j) {
        int col = j * 8 + 2 * lt;
        *(__half2*)&ob[(size_t)lg * HH + col] =
            __floats2half2_rn(oacc[j][0] * il0, oacc[j][1] * il0);
        *(__half2*)&ob[(size_t)(lg + 8) * HH + col] =
            __floats2half2_rn(oacc[j][2] * il1, oacc[j][3] * il1);
    }
}

// ---------------------------------------------------------------------------
extern "C" void kernel_launch(void* const* d_in, const int* in_sizes, int n_in,
                              void* d_out, int out_size)
{
    const float* hs      = (const float*)d_in[0];
    const float* w_qkv   = (const float*)d_in[1];
    const float* b_qkv   = (const float*)d_in[2];
    const float* w_dense = (const float*)d_in[3];
    const int*   pos     = (const int*)d_in[4];
    float* out = (float*)d_out;

    __half *hs_ptr, *qkv_ptr, *attn_ptr, *wt_ptr, *vt_ptr;
    cudaGetSymbolAddress((void**)&hs_ptr, g_hs);
    cudaGetSymbolAddress((void**)&qkv_ptr, g_qkv);
    cudaGetSymbolAddress((void**)&attn_ptr, g_attn);
    cudaGetSymbolAddress((void**)&wt_ptr, g_wt);
    cudaGetSymbolAddress((void**)&vt_ptr, g_vt);

    cudaFuncSetAttribute(mma_gemm_v2<true>,
                         cudaFuncAttributeMaxDynamicSharedMemorySize, G2_SMEM);
    cudaFuncSetAttribute(mma_gemm_v2<false>,
                         cudaFuncAttributeMaxDynamicSharedMemorySize, G2_SMEM);
    cudaFuncSetAttribute(flash_mma_kernel,
                         cudaFuncAttributeMaxDynamicSharedMemorySize, FL_SMEM_BYTES);

    // 1) hidden_states fp32 -> fp16
    f2h_kernel<<<(TOKENS * HH) / (256 * 8), 256>>>(hs, hs_ptr);

    // 2) Transpose + fp16 convert w_qkv
    transpose_f16_kernel<<<dim3(QKV_N / 32, HH / 32), dim3(32, 8)>>>(w_qkv, wt_ptr, HH, QKV_N);

    // 3) QKV projection + bias (cp.async pipelined fp16 GEMM)
    mma_gemm_v2<true><<<dim3(QKV_N / 256, TOKENS / 128), 256, G2_SMEM>>>(
        hs_ptr, wt_ptr, b_qkv, qkv_ptr, TOKENS, QKV_N, HH);

    // 4) RoPE in place (Q and K only)
    {
        int total = TOKENS * (NHEAD + NKVH) * (ROT / 2);
        rope_kernel<<<(total + 255) / 256, 256>>>(qkv_ptr, pos);
    }

    // 5) V transpose
    vtrans_kernel<<<dim3(SS / 32, HDIM / 32, BB * NKVH), dim3(32, 8)>>>(qkv_ptr, vt_ptr);

    // 6) Flash attention
    flash_mma_kernel<<<dim3(SS / 64, BB * NHEAD), 128, FL_SMEM_BYTES>>>(
        qkv_ptr, vt_ptr, attn_ptr);

    // 7) Transpose + fp16 convert w_dense
    transpose_f16_kernel<<<dim3(HH / 32, HH / 32), dim3(32, 8)>>>(w_dense, wt_ptr, HH, HH);

    // 8) Dense projection (cp.async pipelined fp16 GEMM)
    mma_gemm_v2<false><<<dim3(HH / 256, TOKENS / 128), 256, G2_SMEM>>>(
        attn_ptr, wt_ptr, nullptr, out, TOKENS, HH, HH);
}

// round 11
// speedup vs baseline: 1.0359x; 1.0359x over previous
#include <cuda_runtime.h>
#include <cuda_fp16.h>
#include <math.h>
#include <float.h>
#include <cstdint>

// Problem constants
#define BB 2
#define SS 2048
#define HH 4096
#define NHEAD 32
#define NKVH 2
#define HDIM 128
#define ROT 64
#define QKV_N ((NHEAD + 2*NKVH) * HDIM)   // 4608
#define TOKENS (BB*SS)                     // 4096
#define KV_END ((NHEAD + NKVH) * HDIM)     // 4352 (Q+K region; V beyond)

// Scratch (device globals; allocation-free) — all fp16
__device__ __half g_qkv[(size_t)TOKENS * QKV_N];
__device__ __half g_attn[(size_t)TOKENS * HH];
__device__ __half g_wt[(size_t)QKV_N * HH];
__device__ __half g_vt[(size_t)BB * NKVH * HDIM * SS];   // V^T: [b][kvh][d][t]
__device__ float2 g_ropetab[(size_t)TOKENS * 32];         // (cos, sin) per token x pair

// mma.sync m16n8k16 fp16 -> fp32 accum
__device__ __forceinline__ void mma_f16(float* c, const uint32_t* a, const uint32_t* b) {
    asm volatile("mma.sync.aligned.m16n8k16.row.col.f32.f16.f16.f32 "
        "{%0,%1,%2,%3}, {%4,%5,%6,%7}, {%8,%9}, {%0,%1,%2,%3};"
        : "+f"(c[0]), "+f"(c[1]), "+f"(c[2]), "+f"(c[3])
        : "r"(a[0]), "r"(a[1]), "r"(a[2]), "r"(a[3]), "r"(b[0]), "r"(b[1]));
}

__device__ __forceinline__ uint32_t pack_h2(float x, float y) {
    __half2 h = __floats2half2_rn(x, y);
    return *(uint32_t*)&h;
}

__device__ __forceinline__ uint32_t smem_u32(const void* p) {
    uint32_t a;
    asm("{ .reg .u64 t; cvta.to.shared.u64 t, %1; cvt.u32.u64 %0, t; }" : "=r"(a) : "l"(p));
    return a;
}

#define CP16(dst, src) \
    asm volatile("cp.async.cg.shared.global [%0], [%1], 16;" :: "r"(dst), "l"(src) : "memory")
#define CP_COMMIT() asm volatile("cp.async.commit_group;" ::: "memory")
#define CP_WAIT1()  asm volatile("cp.async.wait_group 1;" ::: "memory")
#define CP_WAIT0()  asm volatile("cp.async.wait_group 0;" ::: "memory")

#define LDSM4(r0, r1, r2, r3, addr) \
    asm volatile("ldmatrix.sync.aligned.m8n8.x4.shared.b16 {%0,%1,%2,%3}, [%4];" \
        : "=r"(r0), "=r"(r1), "=r"(r2), "=r"(r3) : "r"(addr))

// ---------------------------------------------------------------------------
// RoPE cos/sin table: tab[tok*32 + i] = (cos, sin)(positions[tok] * 10000^(-i/32))
// ---------------------------------------------------------------------------
__global__ __launch_bounds__(256)
void ropetab_kernel(const int* __restrict__ positions, float2* __restrict__ tab)
{
    int idx = blockIdx.x * 256 + threadIdx.x;    // 0 .. TOKENS*32-1
    int i   = idx & 31;
    int tok = idx >> 5;
    float pos = (float)positions[tok];
    float inv = __powf(10000.0f, -(float)i * (1.0f / 32.0f));
    float ang = pos * inv;
    float c, s;
    sincosf(ang, &s, &c);
    tab[idx] = make_float2(c, s);
}

// ---------------------------------------------------------------------------
// Weight transpose + fp16 convert: W[K,N] fp32 row-major -> Wt[N,K] fp16
// ---------------------------------------------------------------------------
__global__ __launch_bounds__(256)
void transpose_f16_kernel(const float* __restrict__ W, __half* __restrict__ Wt, int K, int N)
{
    __shared__ float t[32][33];
    const int n0 = blockIdx.x * 32;
    const int k0 = blockIdx.y * 32;
    const int x = threadIdx.x, y = threadIdx.y;   // 32 x 8
    #pragma unroll
    for (int j = 0; j < 32; j += 8)
        t[y + j][x] = W[(size_t)(k0 + y + j) * N + n0 + x];
    __syncthreads();
    const int tid = y * 32 + x;
    #pragma unroll
    for (int p = 0; p < 2; ++p) {
        int task = p * 256 + tid;
        int r = task >> 4;
        int c = task & 15;
        __half2 h = __floats2half2_rn(t[2 * c][r], t[2 * c + 1][r]);
        *(__half2*)&Wt[(size_t)(n0 + r) * K + k0 + 2 * c] = h;
    }
}

// ---------------------------------------------------------------------------
// V transpose: g_qkv V region [token][d] -> g_vt [b][kvh][d][token]
// ---------------------------------------------------------------------------
__global__ __launch_bounds__(256)
void vtrans_kernel(const __half* __restrict__ qkv, __half* __restrict__ vt)
{
    __shared__ __half t[32][34];
    const int bk = blockIdx.z;
    const int d0 = blockIdx.y * 32;
    const int t0 = blockIdx.x * 32;
    const int b = bk >> 1, kvh = bk & 1;
    const int x = threadIdx.x, y = threadIdx.y;
    const __half* src = qkv + (size_t)(b * SS + t0) * QKV_N
                        + (NHEAD + NKVH) * HDIM + kvh * HDIM + d0;
    #pragma unroll
    for (int j = 0; j < 32; j += 8)
        t[y + j][x] = src[(size_t)(y + j) * QKV_N + x];
    __syncthreads();
    __half* dst = vt + ((size_t)bk * HDIM + d0) * SS + t0;
    #pragma unroll
    for (int j = 0; j < 32; j += 8)
        dst[(size_t)(y + j) * SS + x] = t[x][y + j];
}

// ---------------------------------------------------------------------------
// fp16 tensor-core GEMM (round-8/9 proven version) + fused RoPE epilogue (QKV)
// BM=128, BN=256, BK=32, 256 thr, 8 warps (2x4), warp tile 64x64, m16n8k16.
// Fragment-order SMEM (uint32 = half2 words), double-buffered.
// QKV mode: A fp32 (cvt on store), C half + bias + RoPE. Dense: A half, C float.
// ---------------------------------------------------------------------------
#define GM_SMEM_WORDS (2*2112 + 2*4352)
#define GM_SMEM_BYTES (GM_SMEM_WORDS * 4)   // 51712

template<bool QKV>
__global__ __launch_bounds__(256, 1)
void mma_gemm_f16(const void* __restrict__ Av, const __half* __restrict__ Bt,
                  const float* __restrict__ bias, const float2* __restrict__ rtab,
                  void* __restrict__ Cv, int M, int N, int K)
{
    extern __shared__ uint32_t smw[];
    uint32_t* Asm = smw;
    uint32_t* Bsm = smw + 4224;

    const float*  Af = (const float*)Av;
    const __half* Ah = (const __half*)Av;

    const int tid  = threadIdx.x;
    const int wid  = tid >> 5;
    const int lane = tid & 31;
    const int lg   = lane >> 2;
    const int lt   = lane & 3;
    const int m_warp = (wid & 1) * 64;
    const int n_warp = (wid >> 1) * 64;
    const int rowBase = blockIdx.y * 128;
    const int colBase = blockIdx.x * 256;

    int fr[4], fq[4];
    #pragma unroll
    for (int p = 0; p < 4; ++p) {
        int idx = p * 256 + tid;
        fr[p] = idx >> 3;
        fq[p] = (idx & 7) * 4;
    }
    int br[8], bq[8];
    #pragma unroll
    for (int p = 0; p < 8; ++p) {
        int idx = p * 256 + tid;
        br[p] = idx >> 3;
        bq[p] = (idx & 7) * 4;
    }

    float acc[4][8][4];
    #pragma unroll
    for (int i = 0; i < 4; ++i)
        #pragma unroll
        for (int j = 0; j < 8; ++j)
            #pragma unroll
            for (int r = 0; r < 4; ++r) acc[i][j][r] = 0.f;

    float4 aSf[4]; uint2 aSh[4]; uint2 bS[8];

    auto ldg_tiles = [&](int kt) {
        #pragma unroll
        for (int p = 0; p < 4; ++p) {
            if (QKV) aSf[p] = *(const float4*)&Af[(size_t)(rowBase + fr[p]) * K + kt + fq[p]];
            else     aSh[p] = *(const uint2*)&Ah[(size_t)(rowBase + fr[p]) * K + kt + fq[p]];
        }
        #pragma unroll
        for (int p = 0; p < 8; ++p)
            bS[p] = *(const uint2*)&Bt[(size_t)(colBase + br[p]) * K + kt + bq[p]];
    };
    auto sts_tiles = [&](int buf) {
        #pragma unroll
        for (int p = 0; p < 4; ++p) {
            int r = fr[p], q = fq[p];
            int lt0 = (q & 7) >> 1;
            int kbit = (q >> 3) & 1;
            uint32_t h0, h1;
            if (QKV) { h0 = pack_h2(aSf[p].x, aSf[p].y); h1 = pack_h2(aSf[p].z, aSf[p].w); }
            else     { h0 = aSh[p].x; h1 = aSh[p].y; }
            int wA = ((r >> 4) * 2 + (q >> 4)) * 132
                     + ((r & 7) * 4 + lt0) * 4 + ((r >> 3) & 1) + 2 * kbit;
            Asm[buf * 2112 + wA]     = h0;
            Asm[buf * 2112 + wA + 4] = h1;
        }
        #pragma unroll
        for (int p = 0; p < 8; ++p) {
            int n = br[p], q = bq[p];
            int lt0 = (q & 7) >> 1;
            int kbit = (q >> 3) & 1;
            int wB = ((n >> 3) * 2 + (q >> 4)) * 68
                     + ((n & 7) * 4 + lt0) * 2 + kbit;
            Bsm[buf * 4352 + wB]     = bS[p].x;
            Bsm[buf * 4352 + wB + 2] = bS[p].y;
        }
    };
    auto mma_tile = [&](int buf) {
        const uint32_t* Ab = Asm + buf * 2112 + (wid & 1) * 1056 + lane * 4;
        const uint32_t* Bb = Bsm + buf * 4352 + (wid >> 1) * 1088 + lane * 2;
        #pragma unroll
        for (int ks = 0; ks < 2; ++ks) {
            uint32_t afr[4][4], bfr[8][2];
            #pragma unroll
            for (int i = 0; i < 4; ++i)
                *(uint4*)afr[i] = *(const uint4*)(Ab + (i * 2 + ks) * 132);
            #pragma unroll
            for (int j = 0; j < 8; ++j)
                *(uint2*)bfr[j] = *(const uint2*)(Bb + (j * 2 + ks) * 68);
            #pragma unroll
            for (int i = 0; i < 4; ++i)
                #pragma unroll
                for (int j = 0; j < 8; ++j)
                    mma_f16(acc[i][j], afr[i], bfr[j]);
        }
    };

    const int NIT = K / 32;
    ldg_tiles(0);
    sts_tiles(0);
    __syncthreads();

    for (int t = 0; t < NIT; ++t) {
        if (t + 1 < NIT) ldg_tiles((t + 1) * 32);
        mma_tile(t & 1);
        if (t + 1 < NIT) sts_tiles((t + 1) & 1);
        __syncthreads();
    }

    #pragma unroll
    for (int i = 0; i < 4; ++i) {
        #pragma unroll
        for (int j = 0; j < 8; ++j) {
            int row = rowBase + m_warp + i * 16 + lg;
            int col = colBase + n_warp + j * 8 + lt * 2;
            if (QKV) {
                __half* C = (__half*)Cv;
                float b0 = bias[col], b1 = bias[col + 1];
                float v0 = acc[i][j][0] + b0, v1 = acc[i][j][1] + b1;
                float v2 = acc[i][j][2] + b0, v3 = acc[i][j][3] + b1;
                // Fused GLM RoPE: Q cols [0,4096) and K cols [4096,4352),
                // first 64 dims of each head, interleaved pairs (col even).
                if (col < KV_END && (col & 127) < ROT) {
                    int ip = (col & 127) >> 1;
                    float2 cs0 = rtab[row * 32 + ip];
                    float2 cs1 = rtab[(row + 8) * 32 + ip];
                    float t0 = v0 * cs0.x - v1 * cs0.y;
                    v1 = v0 * cs0.y + v1 * cs0.x; v0 = t0;
                    float t2 = v2 * cs1.x - v3 * cs1.y;
                    v3 = v2 * cs1.y + v3 * cs1.x; v2 = t2;
                }
                *(__half2*)&C[(size_t)row * N + col]       = __floats2half2_rn(v0, v1);
                *(__half2*)&C[(size_t)(row + 8) * N + col] = __floats2half2_rn(v2, v3);
            } else {
                float* C = (float*)Cv;
                float2 v0 = { acc[i][j][0], acc[i][j][1] };
                float2 v1 = { acc[i][j][2], acc[i][j][3] };
                *(float2*)&C[(size_t)row * N + col]       = v0;
                *(float2*)&C[(size_t)(row + 8) * N + col] = v1;
            }
        }
    }
}

// ---------------------------------------------------------------------------
// Flash attention (round 9 — cp.async + ldmatrix)
// ---------------------------------------------------------------------------
#define FL_K_BYTES 17408
#define FL_V_BYTES 18432
#define FL_SMEM_BYTES (2*FL_K_BYTES + 2*FL_V_BYTES)   // 71680

__global__ __launch_bounds__(128, 3)
void flash_mma_kernel(const __half* __restrict__ qkv, const __half* __restrict__ vt,
                      __half* __restrict__ attn_out)
{
    extern __shared__ uint4 smu[];
    const uint32_t sb = smem_u32(smu);

    const int qt = blockIdx.x;
    const int bh = blockIdx.y;
    const int b  = bh >> 5;
    const int h  = bh & 31;
    const int kvh = h >> 4;
    const int tid = threadIdx.x;
    const int wid = tid >> 5;
    const int lane = tid & 31;
    const int lg = lane >> 2, lt = lane & 3;
    const int gq = lane >> 3, rq = lane & 7;
    const float scale = 0.08838834764831845f;

    const uint4* qg4 = (const uint4*)(qkv + (size_t)(b * SS + qt * 64) * QKV_N + h * HDIM);
    #pragma unroll
    for (int p = 0; p < 8; ++p) {
        int idx = p * 128 + tid;
        smu[(idx >> 4) * 17 + (idx & 15)] = qg4[(size_t)(idx >> 4) * 576 + (idx & 15)];
    }
    __syncthreads();
    uint32_t qa[8][4];
    {
        const uint32_t* Qw = (const uint32_t*)smu;
        int q0 = (wid * 16 + lg) * 68 + lt;
        int q1 = q0 + 8 * 68;
        #pragma unroll
        for (int kc = 0; kc < 8; ++kc) {
            qa[kc][0] = Qw[q0 + kc * 8];
            qa[kc][1] = Qw[q1 + kc * 8];
            qa[kc][2] = Qw[q0 + kc * 8 + 4];
            qa[kc][3] = Qw[q1 + kc * 8 + 4];
        }
    }
    __syncthreads();

    float oacc[16][4];
    #pragma unroll
    for (int j = 0; j < 16; ++j)
        #pragma unroll
        for (int r = 0; r < 4; ++r) oacc[j][r] = 0.f;
    float m0 = -3.0e38f, m1 = -3.0e38f, l0 = 0.f, l1 = 0.f;

    const __half* kbase = qkv + (size_t)b * SS * QKV_N + NHEAD * HDIM + kvh * HDIM;
    const __half* vbase = vt + (size_t)(b * NKVH + kvh) * HDIM * SS;

    auto fill = [&](int kt, int buf) {
        uint32_t Kd = sb + buf * FL_K_BYTES;
        uint32_t Vd = sb + 2 * FL_K_BYTES + buf * FL_V_BYTES;
        const uint4* ks = (const uint4*)(kbase + (size_t)(kt * 64) * QKV_N);
        #pragma unroll
        for (int p = 0; p < 8; ++p) {
            int idx = p * 128 + tid;
            int n = idx >> 4, c = idx & 15;
            CP16(Kd + (uint32_t)(n * 17 + c) * 16, ks + (size_t)n * 576 + c);
        }
        const uint4* vs = (const uint4*)(vbase + kt * 64);
        #pragma unroll
        for (int p = 0; p < 8; ++p) {
            int idx = p * 128 + tid;
            int f = idx >> 3, c = idx & 7;
            CP16(Vd + (uint32_t)(f * 9 + c) * 16, vs + (size_t)f * 256 + c);
        }
    };

    fill(0, 0);
    CP_COMMIT();

    const int row0g = qt * 64 + wid * 16 + lg;
    const int row1g = row0g + 8;

    for (int kt = 0; kt <= qt; ++kt) {
        if (kt < qt) { fill(kt + 1, (kt + 1) & 1); CP_COMMIT(); CP_WAIT1(); }
        else         { CP_WAIT0(); }
        __syncthreads();

        const uint32_t Kb = sb + (kt & 1) * FL_K_BYTES
                            + rq * 272 + (gq >> 1) * 32 + (gq & 1) * 16;
        const uint32_t Vb = sb + 2 * FL_K_BYTES + (kt & 1) * FL_V_BYTES
                            + rq * 144 + (gq >> 1) * 32 + (gq & 1) * 16;

        float sacc[8][4];
        #pragma unroll
        for (int j = 0; j < 8; ++j)
            #pragma unroll
            for (int r = 0; r < 4; ++r) sacc[j][r] = 0.f;

        #pragma unroll
        for (int kp2 = 0; kp2 < 4; ++kp2) {
            #pragma unroll
            for (int j = 0; j < 8; ++j) {
                uint32_t b0, b1, b2, b3;
                LDSM4(b0, b1, b2, b3, Kb + j * 2176 + kp2 * 64);
                uint32_t be[2] = { b0, b1 }, bo[2] = { b2, b3 };
                mma_f16(sacc[j], qa[2 * kp2],     be);
                mma_f16(sacc[j], qa[2 * kp2 + 1], bo);
            }
        }

        #pragma unroll
        for (int j = 0; j < 8; ++j)
            #pragma unroll
            for (int r = 0; r < 4; ++r) sacc[j][r] *= scale;
        if (kt == qt) {
            #pragma unroll
            for (int j = 0; j < 8; ++j) {
                int col = kt * 64 + j * 8 + 2 * lt;
                if (col     > row0g) sacc[j][0] = -3.0e38f;
                if (col + 1 > row0g) sacc[j][1] = -3.0e38f;
                if (col     > row1g) sacc[j][2] = -3.0e38f;
                if (col + 1 > row1g) sacc[j][3] = -3.0e38f;
            }
        }

        float mx0 = -3.0e38f, mx1 = -3.0e38f;
        #pragma unroll
        for (int j = 0; j < 8; ++j) {
            mx0 = fmaxf(mx0, fmaxf(sacc[j][0], sacc[j][1]));
            mx1 = fmaxf(mx1, fmaxf(sacc[j][2], sacc[j][3]));
        }
        mx0 = fmaxf(mx0, __shfl_xor_sync(0xffffffffu, mx0, 1));
        mx0 = fmaxf(mx0, __shfl_xor_sync(0xffffffffu, mx0, 2));
        mx1 = fmaxf(mx1, __shfl_xor_sync(0xffffffffu, mx1, 1));
        mx1 = fmaxf(mx1, __shfl_xor_sync(0xffffffffu, mx1, 2));
        float nm0 = fmaxf(m0, mx0), nm1 = fmaxf(m1, mx1);
        float a0 = __expf(m0 - nm0), a1 = __expf(m1 - nm1);
        m0 = nm0; m1 = nm1;
        float rs0 = 0.f, rs1 = 0.f;
        #pragma unroll
        for (int j = 0; j < 8; ++j) {
            sacc[j][0] = __expf(sacc[j][0] - nm0);
            sacc[j][1] = __expf(sacc[j][1] - nm0);
            sacc[j][2] = __expf(sacc[j][2] - nm1);
            sacc[j][3] = __expf(sacc[j][3] - nm1);
            rs0 += sacc[j][0] + sacc[j][1];
            rs1 += sacc[j][2] + sacc[j][3];
        }
        rs0 += __shfl_xor_sync(0xffffffffu, rs0, 1);
        rs0 += __shfl_xor_sync(0xffffffffu, rs0, 2);
        rs1 += __shfl_xor_sync(0xffffffffu, rs1, 1);
        rs1 += __shfl_xor_sync(0xffffffffu, rs1, 2);
        l0 = l0 * a0 + rs0;
        l1 = l1 * a1 + rs1;

        #pragma unroll
        for (int j = 0; j < 16; ++j) {
            oacc[j][0] *= a0; oacc[j][1] *= a0;
            oacc[j][2] *= a1; oacc[j][3] *= a1;
        }

        uint32_t pa[4][4];
        #pragma unroll
        for (int kp = 0; kp < 4; ++kp) {
            pa[kp][0] = pack_h2(sacc[2 * kp][0],     sacc[2 * kp][1]);
            pa[kp][1] = pack_h2(sacc[2 * kp][2],     sacc[2 * kp][3]);
            pa[kp][2] = pack_h2(sacc[2 * kp + 1][0], sacc[2 * kp + 1][1]);
            pa[kp][3] = pack_h2(sacc[2 * kp + 1][2], sacc[2 * kp + 1][3]);
        }

        #pragma unroll
        for (int kp2 = 0; kp2 < 2; ++kp2) {
            #pragma unroll
            for (int jf = 0; jf < 16; ++jf) {
                uint32_t r0, r1, r2, r3;
                LDSM4(r0, r1, r2, r3, Vb + jf * 1152 + kp2 * 64);
                uint32_t ve[2] = { r0, r1 }, vo[2] = { r2, r3 };
                mma_f16(oacc[jf], pa[2 * kp2],     ve);
                mma_f16(oacc[jf], pa[2 * kp2 + 1], vo);
            }
        }
        __syncthreads();
    }

    float il0 = 1.0f / l0, il1 = 1.0f / l1;
    __half* ob = attn_out + (size_t)(b * SS + qt * 64 + wid * 16) * HH + h * HDIM;
    #pragma unroll
    for (int j = 0; j < 16; ++j) {
        int col = j * 8 + 2 * lt;
        *(__half2*)&ob[(size_t)lg * HH + col] =
            __floats2half2_rn(oacc[j][0] * il0, oacc[j][1] * il0);
        *(__half2*)&ob[(size_t)(lg + 8) * HH + col] =
            __floats2half2_rn(oacc[j][2] * il1, oacc[j][3] * il1);
    }
}

// ---------------------------------------------------------------------------
extern "C" void kernel_launch(void* const* d_in, const int* in_sizes, int n_in,
                              void* d_out, int out_size)
{
    const float* hs      = (const float*)d_in[0];
    const float* w_qkv   = (const float*)d_in[1];
    const float* b_qkv   = (const float*)d_in[2];
    const float* w_dense = (const float*)d_in[3];
    const int*   pos     = (const int*)d_in[4];
    float* out = (float*)d_out;

    __half *qkv_ptr, *attn_ptr, *wt_ptr, *vt_ptr;
    float2* rtab_ptr;
    cudaGetSymbolAddress((void**)&qkv_ptr, g_qkv);
    cudaGetSymbolAddress((void**)&attn_ptr, g_attn);
    cudaGetSymbolAddress((void**)&wt_ptr, g_wt);
    cudaGetSymbolAddress((void**)&vt_ptr, g_vt);
    cudaGetSymbolAddress((void**)&rtab_ptr, g_ropetab);

    cudaFuncSetAttribute(mma_gemm_f16<true>,
                         cudaFuncAttributeMaxDynamicSharedMemorySize, GM_SMEM_BYTES);
    cudaFuncSetAttribute(mma_gemm_f16<false>,
                         cudaFuncAttributeMaxDynamicSharedMemorySize, GM_SMEM_BYTES);
    cudaFuncSetAttribute(flash_mma_kernel,
                         cudaFuncAttributeMaxDynamicSharedMemorySize, FL_SMEM_BYTES);

    // 1) RoPE cos/sin table
    ropetab_kernel<<<(TOKENS * 32) / 256, 256>>>(pos, rtab_ptr);

    // 2) Transpose + fp16 convert w_qkv
    transpose_f16_kernel<<<dim3(QKV_N / 32, HH / 32), dim3(32, 8)>>>(w_qkv, wt_ptr, HH, QKV_N);

    // 3) QKV projection + bias + fused RoPE (fp16 tensor cores; A fp32 in)
    mma_gemm_f16<true><<<dim3(QKV_N / 256, TOKENS / 128), 256, GM_SMEM_BYTES>>>(
        hs, wt_ptr, b_qkv, rtab_ptr, qkv_ptr, TOKENS, QKV_N, HH);

    // 4) V transpose (V untouched by RoPE)
    vtrans_kernel<<<dim3(SS / 32, HDIM / 32, BB * NKVH), dim3(32, 8)>>>(qkv_ptr, vt_ptr);

    // 5) Flash attention (cp.async + ldmatrix)
    flash_mma_kernel<<<dim3(SS / 64, BB * NHEAD), 128, FL_SMEM_BYTES>>>(
        qkv_ptr, vt_ptr, attn_ptr);

    // 6) Transpose + fp16 convert w_dense
    transpose_f16_kernel<<<dim3(HH / 32, HH / 32), dim3(32, 8)>>>(w_dense, wt_ptr, HH, HH);

    // 7) Dense projection (fp16 tensor cores; C fp32 out)
    mma_gemm_f16<false><<<dim3(HH / 256, TOKENS / 128), 256, GM_SMEM_BYTES>>>(
        attn_ptr, wt_ptr, nullptr, nullptr, out, TOKENS, HH, HH);
}